// round 15
// baseline (speedup 1.0000x reference)
#include <cuda_runtime.h>
#include <cuda_bf16.h>

#define EMB       512
#define N_NODES   16384
#define N_PAIRS   200000
#define MAX_EVENTS 1000000
#define SC_BLK    296
#define SC_THR    768

// Scratch (device globals — no allocation allowed)
__device__ float  g_node_mean[N_NODES];
__device__ __align__(16) float2 g_pair[N_PAIRS];    // x = event-sum, y = count
__device__ __align__(16) float2 g_place[N_NODES];   // x = pair-mean sum, y = count
__device__ __align__(16) int    g_evt_off[MAX_EVENTS];

// Vectorized float2 reduction (one L2 atomic op for sum+count)
__device__ __forceinline__ void red_add_v2(float2* addr, float a, float b) {
    asm volatile("red.global.add.v2.f32 [%0], {%1, %2};"
                 :: "l"(addr), "f"(a), "f"(b) : "memory");
}

// ---------------------------------------------------------------------------
// K1: zero accumulators; evt_off boundary scan (dst_event sorted, int4);
//     node_mean (one warp per row, float4).   grid = 2048 x 256   [R5-proven]
// ---------------------------------------------------------------------------
__global__ void k_prep(const float* __restrict__ emb,
                       const int* __restrict__ dst_event,
                       int n_dst) {
    int tid = blockIdx.x * blockDim.x + threadIdx.x;
    int stride = gridDim.x * blockDim.x;

    float4 z = make_float4(0.f, 0.f, 0.f, 0.f);
    float4* gp = reinterpret_cast<float4*>(g_pair);
    for (int j = tid; j < N_PAIRS / 2; j += stride) gp[j] = z;
    float4* gl = reinterpret_cast<float4*>(g_place);
    for (int j = tid; j < N_NODES / 2; j += stride) gl[j] = z;

    int n_grp = (n_dst + 3) >> 2;
    const int4* de4 = reinterpret_cast<const int4*>(dst_event);
    for (int g = tid; g < n_grp; g += stride) {
        int base = g << 2;
        if (base + 3 < n_dst) {
            int4 v = de4[g];
            int prev = (base == 0) ? -1 : __ldg(&dst_event[base - 1]);
            if (v.x != prev) g_evt_off[v.x] = base;
            if (v.y != v.x)  g_evt_off[v.y] = base + 1;
            if (v.z != v.y)  g_evt_off[v.z] = base + 2;
            if (v.w != v.z)  g_evt_off[v.w] = base + 3;
        } else {
            for (int i = base; i < n_dst; i++) {
                int e = dst_event[i];
                int prev = (i == 0) ? -1 : dst_event[i - 1];
                if (e != prev) g_evt_off[e] = i;
            }
        }
    }

    int row = tid >> 5;
    int lane = tid & 31;
    const float4* r = reinterpret_cast<const float4*>(emb + (size_t)row * EMB);
    float s = 0.0f;
    #pragma unroll
    for (int k = 0; k < 4; k++) {
        float4 v = r[lane + 32 * k];
        s += (v.x + v.y) + (v.z + v.w);
    }
    #pragma unroll
    for (int off = 16; off > 0; off >>= 1)
        s += __shfl_down_sync(0xffffffffu, s, off);
    if (lane == 0)
        g_node_mean[row] = s * (1.0f / EMB);
}

// ---------------------------------------------------------------------------
// K2: scatter with node_mean staged in smem (R5-proven scalar loop).
//   296 blocks x 768 thr, 64KB smem, 2 blocks/SM = same 1536 thr/SM occupancy
//   as 444x512x3, but 33% less staging traffic (296 vs 444 table copies).
//   one red.v2 per event: pair[p] += { nm[src] + (sum nm[dst])/(nd+1), 1 }
// ---------------------------------------------------------------------------
__global__ void __launch_bounds__(SC_THR, 2)
k_scatter(const int* __restrict__ event_pair,
          const int* __restrict__ event_src,
          const int* __restrict__ event_ndst,
          const int* __restrict__ dst_node,
          int n_events) {
    extern __shared__ float s_nm[];   // 64KB
    {
        // 16384 floats = 4096 float4; 768 threads -> 6 iterations (last partial)
        const float4* src = reinterpret_cast<const float4*>(g_node_mean);
        float4* dst = reinterpret_cast<float4*>(s_nm);
        for (int k = threadIdx.x; k < N_NODES / 4; k += SC_THR)
            dst[k] = src[k];
    }
    __syncthreads();

    const int tid = blockIdx.x * SC_THR + threadIdx.x;
    const int stride = SC_BLK * SC_THR;

    for (int e = tid; e < n_events; e += stride) {
        int p   = event_pair[e];
        int nd  = event_ndst[e];
        int off = g_evt_off[e];

        // nd in [1,4]: predicated fixed-trip loop, independent smem gathers
        float dsum = 0.0f;
        #pragma unroll
        for (int j = 0; j < 4; j++) {
            float v = (j < nd) ? s_nm[__ldg(&dst_node[off + j])] : 0.0f;
            dsum += v;
        }

        float val = s_nm[event_src[e]] + dsum / ((float)nd + 1.0f);
        red_add_v2(&g_pair[p], val, 1.0f);
    }
}

// ---------------------------------------------------------------------------
// K3: pair -> place, ONE pair per thread (200k threads; latency-bound kernel
//     needs warps, not ILP).  pair_mean = (sum/cnt + nm[place]) / 3
// ---------------------------------------------------------------------------
__global__ void k_pair_to_place(const int* __restrict__ pair_place) {
    int p = blockIdx.x * blockDim.x + threadIdx.x;
    if (p >= N_PAIRS) return;
    float2 a = g_pair[p];
    int pl = pair_place[p];
    if (a.y > 0.0f) {
        float pm = (a.x / a.y + __ldg(&g_node_mean[pl])) * (1.0f / 3.0f);
        red_add_v2(&g_place[pl], pm, 1.0f);
    }
}

// ---------------------------------------------------------------------------
// K4: broadcast fill — one warp per row, 12 independent STG.128 per lane.
//     At the chip store-path cap (~6.1TB/s); this is the floor.
// ---------------------------------------------------------------------------
__global__ void k_fill_out(float* __restrict__ out) {
    int tid = blockIdx.x * blockDim.x + threadIdx.x;
    int row = tid >> 5;
    int lane = tid & 31;
    float2 a = g_place[row];
    float v = (a.y > 0.0f) ? (a.x / a.y) : 0.0f;
    float4 v4 = make_float4(v, v, v, v);
    float4* o = reinterpret_cast<float4*>(out + (size_t)row * (3 * EMB));
    #pragma unroll
    for (int k = 0; k < 12; k++)
        o[lane + 32 * k] = v4;
}

// ---------------------------------------------------------------------------
extern "C" void kernel_launch(void* const* d_in, const int* in_sizes, int n_in,
                              void* d_out, int out_size) {
    const float* embeddings = (const float*)d_in[0];
    const int* pair_place   = (const int*)d_in[1];
    const int* event_pair   = (const int*)d_in[2];
    const int* event_src    = (const int*)d_in[3];
    const int* event_ndst   = (const int*)d_in[4];
    const int* dst_event    = (const int*)d_in[5];
    const int* dst_node     = (const int*)d_in[6];
    float* out = (float*)d_out;

    int n_events = in_sizes[2];
    int n_dst = in_sizes[5];

    const int SMEM = N_NODES * (int)sizeof(float);   // 64KB
    cudaFuncSetAttribute(k_scatter,
                         cudaFuncAttributeMaxDynamicSharedMemorySize, SMEM);

    k_prep<<<2048, 256>>>(embeddings, dst_event, n_dst);
    k_scatter<<<SC_BLK, SC_THR, SMEM>>>(event_pair, event_src, event_ndst,
                                        dst_node, n_events);
    k_pair_to_place<<<(N_PAIRS + 255) / 256, 256>>>(pair_place);
    k_fill_out<<<2048, 256>>>(out);
}

// round 16
// speedup vs baseline: 1.0415x; 1.0415x over previous
#include <cuda_runtime.h>
#include <cuda_bf16.h>

#define EMB       512
#define N_NODES   16384
#define N_PAIRS   200000
#define MAX_EVENTS 1000000
#define SC_BLK    444
#define SC_THR    512

// Scratch (device globals — no allocation allowed)
__device__ float  g_node_mean[N_NODES];
__device__ __align__(16) float2 g_pair[N_PAIRS];    // x = event-sum, y = count
__device__ __align__(16) float2 g_place[N_NODES];   // x = pair-mean sum, y = count
__device__ __align__(16) int    g_evt_off[MAX_EVENTS];

// Vectorized float2 reduction (one L2 atomic op for sum+count)
__device__ __forceinline__ void red_add_v2(float2* addr, float a, float b) {
    asm volatile("red.global.add.v2.f32 [%0], {%1, %2};"
                 :: "l"(addr), "f"(a), "f"(b) : "memory");
}

// ---------------------------------------------------------------------------
// K1: zero accumulators; evt_off boundary scan (dst_event sorted, int4);
//     node_mean (one warp per row, float4).   grid = 2048 x 256
// ---------------------------------------------------------------------------
__global__ void k_prep(const float* __restrict__ emb,
                       const int* __restrict__ dst_event,
                       int n_dst) {
    int tid = blockIdx.x * blockDim.x + threadIdx.x;
    int stride = gridDim.x * blockDim.x;

    float4 z = make_float4(0.f, 0.f, 0.f, 0.f);
    float4* gp = reinterpret_cast<float4*>(g_pair);
    for (int j = tid; j < N_PAIRS / 2; j += stride) gp[j] = z;
    float4* gl = reinterpret_cast<float4*>(g_place);
    for (int j = tid; j < N_NODES / 2; j += stride) gl[j] = z;

    int n_grp = (n_dst + 3) >> 2;
    const int4* de4 = reinterpret_cast<const int4*>(dst_event);
    for (int g = tid; g < n_grp; g += stride) {
        int base = g << 2;
        if (base + 3 < n_dst) {
            int4 v = de4[g];
            int prev = (base == 0) ? -1 : __ldg(&dst_event[base - 1]);
            if (v.x != prev) g_evt_off[v.x] = base;
            if (v.y != v.x)  g_evt_off[v.y] = base + 1;
            if (v.z != v.y)  g_evt_off[v.z] = base + 2;
            if (v.w != v.z)  g_evt_off[v.w] = base + 3;
        } else {
            for (int i = base; i < n_dst; i++) {
                int e = dst_event[i];
                int prev = (i == 0) ? -1 : dst_event[i - 1];
                if (e != prev) g_evt_off[e] = i;
            }
        }
    }

    int row = tid >> 5;
    int lane = tid & 31;
    const float4* r = reinterpret_cast<const float4*>(emb + (size_t)row * EMB);
    float s = 0.0f;
    #pragma unroll
    for (int k = 0; k < 4; k++) {
        float4 v = r[lane + 32 * k];
        s += (v.x + v.y) + (v.z + v.w);
    }
    #pragma unroll
    for (int off = 16; off > 0; off >>= 1)
        s += __shfl_down_sync(0xffffffffu, s, off);
    if (lane == 0)
        g_node_mean[row] = s * (1.0f / EMB);
}

// ---------------------------------------------------------------------------
// K2: scatter with node_mean staged in smem.
//   444 blocks x 512 thr, 64KB smem, 3 blocks/SM.
//   one red.v2 per event: pair[p] += { nm[src] + (sum nm[dst])/(nd+1), 1 }
// ---------------------------------------------------------------------------
__global__ void __launch_bounds__(SC_THR, 3)
k_scatter(const int* __restrict__ event_pair,
          const int* __restrict__ event_src,
          const int* __restrict__ event_ndst,
          const int* __restrict__ dst_node,
          int n_events) {
    extern __shared__ float s_nm[];   // 64KB
    {
        const float4* src = reinterpret_cast<const float4*>(g_node_mean);
        float4* dst = reinterpret_cast<float4*>(s_nm);
        int t = threadIdx.x;
        #pragma unroll
        for (int k = 0; k < N_NODES / 4 / SC_THR; k++)
            dst[t + SC_THR * k] = src[t + SC_THR * k];
    }
    __syncthreads();

    const int tid = blockIdx.x * SC_THR + threadIdx.x;
    const int stride = SC_BLK * SC_THR;

    for (int e = tid; e < n_events; e += stride) {
        int p   = event_pair[e];
        int nd  = event_ndst[e];
        int off = g_evt_off[e];

        // nd in [1,4]: predicated fixed-trip loop, independent smem gathers
        float dsum = 0.0f;
        #pragma unroll
        for (int j = 0; j < 4; j++) {
            float v = (j < nd) ? s_nm[__ldg(&dst_node[off + j])] : 0.0f;
            dsum += v;
        }

        float val = s_nm[event_src[e]] + dsum / ((float)nd + 1.0f);
        red_add_v2(&g_pair[p], val, 1.0f);
    }
}

// ---------------------------------------------------------------------------
// K3: pair -> place (2 pairs/thread).  pair_mean = (sum/cnt + nm[place]) / 3
// ---------------------------------------------------------------------------
__global__ void k_pair_to_place(const int* __restrict__ pair_place) {
    int t = blockIdx.x * blockDim.x + threadIdx.x;
    if (t >= N_PAIRS / 2) return;
    float4 a = reinterpret_cast<const float4*>(g_pair)[t];
    int2 pl = reinterpret_cast<const int2*>(pair_place)[t];
    if (a.y > 0.0f) {
        float pm = (a.x / a.y + __ldg(&g_node_mean[pl.x])) * (1.0f / 3.0f);
        red_add_v2(&g_place[pl.x], pm, 1.0f);
    }
    if (a.w > 0.0f) {
        float pm = (a.z / a.w + __ldg(&g_node_mean[pl.y])) * (1.0f / 3.0f);
        red_add_v2(&g_place[pl.y], pm, 1.0f);
    }
}

// ---------------------------------------------------------------------------
// K4: broadcast fill — one warp per row, 12 independent STG.128 per lane.
//     At the chip store-path cap (~6.1TB/s); this is the floor.
// ---------------------------------------------------------------------------
__global__ void k_fill_out(float* __restrict__ out) {
    int tid = blockIdx.x * blockDim.x + threadIdx.x;
    int row = tid >> 5;
    int lane = tid & 31;
    float2 a = g_place[row];
    float v = (a.y > 0.0f) ? (a.x / a.y) : 0.0f;
    float4 v4 = make_float4(v, v, v, v);
    float4* o = reinterpret_cast<float4*>(out + (size_t)row * (3 * EMB));
    #pragma unroll
    for (int k = 0; k < 12; k++)
        o[lane + 32 * k] = v4;
}

// ---------------------------------------------------------------------------
extern "C" void kernel_launch(void* const* d_in, const int* in_sizes, int n_in,
                              void* d_out, int out_size) {
    const float* embeddings = (const float*)d_in[0];
    const int* pair_place   = (const int*)d_in[1];
    const int* event_pair   = (const int*)d_in[2];
    const int* event_src    = (const int*)d_in[3];
    const int* event_ndst   = (const int*)d_in[4];
    const int* dst_event    = (const int*)d_in[5];
    const int* dst_node     = (const int*)d_in[6];
    float* out = (float*)d_out;

    int n_events = in_sizes[2];
    int n_dst = in_sizes[5];

    const int SMEM = N_NODES * (int)sizeof(float);   // 64KB
    cudaFuncSetAttribute(k_scatter,
                         cudaFuncAttributeMaxDynamicSharedMemorySize, SMEM);

    k_prep<<<2048, 256>>>(embeddings, dst_event, n_dst);
    k_scatter<<<SC_BLK, SC_THR, SMEM>>>(event_pair, event_src, event_ndst,
                                        dst_node, n_events);
    k_pair_to_place<<<(N_PAIRS / 2 + 255) / 256, 256>>>(pair_place);
    k_fill_out<<<2048, 256>>>(out);
}